// round 16
// baseline (speedup 1.0000x reference)
#include <cuda_runtime.h>
#include <cuda_fp16.h>
#include <math.h>
#include <stdint.h>

#define Hx 24
#define Dx 128
#define NHx 4
#define DHx 32
#define RS32 0.17677669529663687f

// ------------------------- device globals -------------------------
__device__ float g_E[2][3][Hx][Dx];
__device__ float g_Gt[2][Hx][NHx*Hx];
__device__ float g_Mkt[2][Hx][NHx*Hx];
__device__ float g_gq[2][NHx][Hx];
__device__ float g_gk[2][NHx][Hx];
__device__ __align__(16) __half g_Ph[2][Dx][104];
__device__ float g_Pc[2][Dx];
__device__ float g_gw[2][Dx];
__device__ float g_sc[2][2];
__device__ __half g_th[2][2][25165824u];   // [br][hi/lo plane][row*128+c]
__device__ __half g_w1h[512][128];
__device__ __half g_w2h[128][512];

// ------------------------- helpers -------------------------
__device__ __forceinline__ uint32_t cvta_s(const void* p) {
    uint32_t a;
    asm("{ .reg .u64 t; cvta.to.shared.u64 t, %1; cvt.u32.u64 %0, t; }" : "=r"(a) : "l"(p));
    return a;
}
__device__ __forceinline__ void ldsm4(uint32_t addr, uint32_t& r0, uint32_t& r1,
                                      uint32_t& r2, uint32_t& r3) {
    asm volatile("ldmatrix.sync.aligned.m8n8.x4.shared.b16 {%0,%1,%2,%3}, [%4];"
                 : "=r"(r0), "=r"(r1), "=r"(r2), "=r"(r3) : "r"(addr));
}
__device__ __forceinline__ void mma_f16(float d[4], uint32_t a0, uint32_t a1, uint32_t a2,
                                        uint32_t a3, uint32_t b0, uint32_t b1) {
    asm volatile("mma.sync.aligned.m16n8k16.row.col.f32.f16.f16.f32 "
                 "{%0,%1,%2,%3}, {%4,%5,%6,%7}, {%8,%9}, {%0,%1,%2,%3};"
                 : "+f"(d[0]), "+f"(d[1]), "+f"(d[2]), "+f"(d[3])
                 : "r"(a0), "r"(a1), "r"(a2), "r"(a3), "r"(b0), "r"(b1));
}
__device__ __forceinline__ void mma_f16h(uint32_t d[2], uint32_t a0, uint32_t a1, uint32_t a2,
                                         uint32_t a3, uint32_t b0, uint32_t b1) {
    asm volatile("mma.sync.aligned.m16n8k16.row.col.f16.f16.f16.f16 "
                 "{%0,%1}, {%2,%3,%4,%5}, {%6,%7}, {%0,%1};"
                 : "+r"(d[0]), "+r"(d[1])
                 : "r"(a0), "r"(a1), "r"(a2), "r"(a3), "r"(b0), "r"(b1));
}
__device__ __forceinline__ uint32_t pk2h(__half e0, __half e1) {
    return (uint32_t)__half_as_ushort(e0) | ((uint32_t)__half_as_ushort(e1) << 16);
}
__device__ __forceinline__ float hLO(uint32_t v) {
    return __half2float(__ushort_as_half((unsigned short)(v & 0xFFFFu)));
}
__device__ __forceinline__ float hHI(uint32_t v) {
    return __half2float(__ushort_as_half((unsigned short)(v >> 16)));
}
__device__ __forceinline__ uint32_t relu_add_h2(uint32_t a, uint32_t b) {
    __half2 r = __hmax2(__hadd2(*(__half2*)&a, *(__half2*)&b),
                        __floats2half2_rn(0.f, 0.f));
    return *(uint32_t*)&r;
}
#define CPA16(d, s) asm volatile("cp.async.cg.shared.global [%0], [%1], 16;" :: "r"(d), "l"(s))
#define CPA_COMMIT() asm volatile("cp.async.commit_group;" ::: "memory")

// ------------------------- precompute 1 -------------------------
__global__ void pre_qkv(const float* __restrict__ fe, const float* __restrict__ inwp,
                        const float* __restrict__ inwf) {
    int br = blockIdx.x / 3, which = blockIdx.x % 3;
    const float* W = (br ? inwf : inwp) + which * Dx * Dx;
    __shared__ float fes[Hx * Dx];
    for (int idx = threadIdx.x; idx < Hx * Dx; idx += 256) fes[idx] = fe[idx];
    __syncthreads();
    for (int idx = blockIdx.y * 256 + threadIdx.x; idx < Hx * Dx; idx += 2048) {
        int i = idx >> 7, c = idx & 127;
        float s = 0.f;
        #pragma unroll 8
        for (int d = 0; d < Dx; d++) s += fes[i * Dx + d] * W[c * Dx + d];
        g_E[br][which][i][c] = s;
    }
}

// ------------------------- precompute 2 -------------------------
__global__ void pre_misc(const float* __restrict__ inbp, const float* __restrict__ inbf,
                         const float* __restrict__ outwp, const float* __restrict__ outbp,
                         const float* __restrict__ outwf, const float* __restrict__ outbf,
                         const float* __restrict__ ln2g, const float* __restrict__ ln2b,
                         const float* __restrict__ oppw, const float* __restrict__ oppb,
                         const float* __restrict__ opfw, const float* __restrict__ opfb,
                         const float* __restrict__ alog,
                         const float* __restrict__ biasp, const float* __restrict__ biasf) {
    int br = blockIdx.x, gy = blockIdx.y;
    const float* inb  = br ? inbf  : inbp;
    const float* outw = br ? outwf : outwp;
    const float* outb = br ? outbf : outbp;
    const float* opw  = br ? opfw  : oppw;
    const float* opb  = br ? opfb  : oppb;
    const float* bias = br ? biasf : biasp;
    const float* qb = inb, *kb = inb + Dx, *vb = inb + 2 * Dx;
    __shared__ float g0s[NHx];
    int tid = threadIdx.x;
    if (tid < NHx) {
        float s = 0.f;
        for (int d = 0; d < DHx; d++) s += qb[tid * DHx + d] * kb[tid * DHx + d];
        g0s[tid] = s * RS32;
    }
    __syncthreads();
    int base = gy * 256 + tid;
    for (int idx = base; idx < NHx * Hx; idx += 2048) {
        int n = idx / Hx, i = idx % Hx;
        float s1 = 0.f, s2 = 0.f;
        for (int d = 0; d < DHx; d++) {
            s1 += g_E[br][0][i][n * DHx + d] * kb[n * DHx + d];
            s2 += g_E[br][1][i][n * DHx + d] * qb[n * DHx + d];
        }
        g_gq[br][n][i] = s1 * RS32;
        g_gk[br][n][i] = s2 * RS32;
    }
    for (int idx = base; idx < NHx * Hx * Hx; idx += 2048) {
        int n = idx / (Hx * Hx), i = (idx / Hx) % Hx, j = idx % Hx;
        float s = 0.f;
        for (int d = 0; d < DHx; d++)
            s += g_E[br][0][i][n * DHx + d] * g_E[br][1][j][n * DHx + d];
        g_Gt[br][j][n * Hx + i] = s * RS32;
        bool valid = (br == 0) ? (j <= i) : (j >= i);
        g_Mkt[br][j][n * Hx + i] = valid ? bias[j - i + Hx - 1] + g0s[n] : -1e30f;
    }
    for (int idx = base; idx < NHx * Hx * Dx; idx += 2048) {
        int k = idx >> 7, c = idx & 127;
        int n = k / Hx, j = k % Hx;
        float s = 0.f;
        for (int d = 0; d < DHx; d++)
            s += outw[c * Dx + n * DHx + d] * g_E[br][2][j][n * DHx + d];
        g_Ph[br][c][k] = __float2half_rn(s);
    }
    if (gy == 0) {
        float e0 = expf(alog[0]), e1 = expf(alog[1]);
        float alpha = (br == 0 ? e0 : e1) / (e0 + e1);
        for (int idx = tid; idx < Dx; idx += 256) {
            float s = outb[idx];
            for (int m = 0; m < Dx; m++) s += outw[idx * Dx + m] * vb[m];
            g_Pc[br][idx] = s;
            g_gw[br][idx] = ln2g[idx] * opw[idx] * alpha;
        }
        __syncthreads();
        __threadfence();
        if (tid == 0) {
            float sgw = 0.f, cst = 0.f;
            for (int c = 0; c < Dx; c++) { sgw += g_gw[br][c]; cst += ln2b[c] * opw[c]; }
            g_sc[br][0] = sgw;
            g_sc[br][1] = alpha * (cst + opb[0]);
        }
    }
}

// ------------------------- precompute 3: fp16 weight images -------------------------
__global__ void pre_wimg(const float* __restrict__ w1, const float* __restrict__ w2) {
    int idx = blockIdx.x * 256 + threadIdx.x;
    if (idx >= 65536) return;
    {
        int f = idx >> 7, c = idx & 127;
        g_w1h[f][c] = __float2half_rn(w1[idx]);
    }
    {
        int n = idx >> 9, ff = idx & 511;
        g_w2h[n][ff] = __float2half_rn(w2[idx]);
    }
}

// ------------------------- K2: attention (fp16-acc mma) + LN1 -> hi/lo planes ----------
#define FE0 480
#define WH0 3672
#define PH0 8664
#define K2BYTES 61280

__global__ __launch_bounds__(256, 3)
void attn_k(const float* __restrict__ z, const float* __restrict__ fe,
            const float* __restrict__ ln1g, const float* __restrict__ ln1b,
            float* __restrict__ out) {
    extern __shared__ float sm[];
    float* zsm  = sm;
    float* c1g  = sm + 96;
    float* c1b  = sm + 224;
    float* pcs  = sm + 352;
    float* fesm = sm + FE0;
    __half* Wh  = (__half*)(sm + WH0);
    uint32_t sb = cvta_s(sm);
    uint32_t WhB = sb + WH0 * 4;
    uint32_t PhB = sb + PH0 * 4;
    int tid = threadIdx.x, wid = tid >> 5, lane = tid & 31;
    int g = lane >> 3;
    int blk = blockIdx.x;

    if (tid < 96) { zsm[tid] = z[blk * 96 + tid]; out[blk * 96 + tid] = 0.f; }
    if (tid >= 128) { c1g[tid - 128] = ln1g[tid - 128]; c1b[tid - 128] = ln1b[tid - 128]; }
    for (int idx = tid; idx < Hx * Dx; idx += 256)
        fesm[(idx >> 7) * 133 + (idx & 127)] = fe[idx];
    __syncthreads();

    for (int br = 0; br < 2; br++) {
        {
            const uint4* ps = (const uint4*)&g_Ph[br][0][0];
            uint4* pd = (uint4*)(sm + PH0);
            for (int i = tid; i < 1664; i += 256) pd[i] = ps[i];
            if (tid < 128) pcs[tid] = g_Pc[br][tid];
        }
        for (int rs = tid; rs < 384; rs += 256) {
            int bb = rs / 96, rem = rs % 96, n = rem / 24, i = rem % 24;
            int x = n * Hx + i;
            float zi = zsm[bb * 24 + i];
            const float* Gt = &g_Gt[br][0][x];
            const float* Mt = &g_Mkt[br][0][x];
            const float* gkp = &g_gk[br][n][0];
            float gq = g_gq[br][n][i];
            float s[24]; float mx = -1e30f;
            #pragma unroll
            for (int j = 0; j < 24; j++) {
                float zj = zsm[bb * 24 + j];
                float v = zi * zj * Gt[j * 96] + zi * gq + zj * gkp[j] + Mt[j * 96];
                s[j] = v; mx = fmaxf(mx, v);
            }
            float sum = 0.f;
            #pragma unroll
            for (int j = 0; j < 24; j++) { s[j] = __expf(fmaxf(s[j] - mx, -80.f)); sum += s[j]; }
            float inv = 1.f / sum;
            __half* wrow = &Wh[(bb * 24 + i) * 104 + n * 24];
            #pragma unroll
            for (int j = 0; j < 24; j += 2) {
                *(uint32_t*)&wrow[j] = pk2h(__float2half_rn(s[j] * inv * zsm[bb * 24 + j]),
                                            __float2half_rn(s[j + 1] * inv * zsm[bb * 24 + j + 1]));
            }
        }
        __syncthreads();

        if (wid < 6) {
            uint32_t accOh[16][2];
            #pragma unroll
            for (int q = 0; q < 16; q++) { accOh[q][0] = 0u; accOh[q][1] = 0u; }
            uint32_t aAddr = WhB + (uint32_t)(wid * 16 + (lane & 7) + ((g & 1) << 3)) * 208u
                                 + (uint32_t)((g >> 1) << 4);
            uint32_t bAddr = PhB + (uint32_t)((lane & 7) + ((g >> 1) << 3)) * 208u
                                 + (uint32_t)((g & 1) << 4);
            #pragma unroll
            for (int k = 0; k < 6; k++) {
                uint32_t a0, a1, a2, a3;
                ldsm4(aAddr + (uint32_t)k * 32u, a0, a1, a2, a3);
                #pragma unroll
                for (int q = 0; q < 8; q++) {
                    uint32_t r0, r1, r2, r3;
                    ldsm4(bAddr + (uint32_t)(q * 16 * 208) + (uint32_t)k * 32u, r0, r1, r2, r3);
                    mma_f16h(accOh[2 * q],     a0, a1, a2, a3, r0, r1);
                    mma_f16h(accOh[2 * q + 1], a0, a1, a2, a3, r2, r3);
                }
            }
            int ra = wid * 16 + (lane >> 2);
            int rb = ra + 8;
            int iiA = ra % 24, iiB = rb % 24;
            float zA = zsm[ra], zB = zsm[rb];
            // pass 1: LN1 stats (y recomputed transiently)
            float sA0 = 0.f, sA1 = 0.f, sB0 = 0.f, sB1 = 0.f;
            #pragma unroll
            for (int t = 0; t < 16; t++) {
                int c = t * 8 + ((lane & 3) << 1);
                float pc0 = pcs[c], pc1 = pcs[c + 1];
                float y0 = hLO(accOh[t][0]) + pc0 + zA * fesm[iiA * 133 + c];
                float y1 = hHI(accOh[t][0]) + pc1 + zA * fesm[iiA * 133 + c + 1];
                float y2 = hLO(accOh[t][1]) + pc0 + zB * fesm[iiB * 133 + c];
                float y3 = hHI(accOh[t][1]) + pc1 + zB * fesm[iiB * 133 + c + 1];
                sA0 += y0 + y1; sA1 += y0 * y0 + y1 * y1;
                sB0 += y2 + y3; sB1 += y2 * y2 + y3 * y3;
            }
            #pragma unroll
            for (int m = 1; m < 4; m <<= 1) {
                sA0 += __shfl_xor_sync(0xffffffffu, sA0, m);
                sA1 += __shfl_xor_sync(0xffffffffu, sA1, m);
                sB0 += __shfl_xor_sync(0xffffffffu, sB0, m);
                sB1 += __shfl_xor_sync(0xffffffffu, sB1, m);
            }
            float mA = sA0 * (1.f / 128.f);
            float rA = rsqrtf(sA1 * (1.f / 128.f) - mA * mA + 1e-5f);
            float mB = sB0 * (1.f / 128.f);
            float rB = rsqrtf(sB1 * (1.f / 128.f) - mB * mB + 1e-5f);
            // pass 2: recompute y, normalize, split hi/lo, store planes
            size_t rowA = (size_t)(blk * 96 + ra) * 128;
            size_t rowB = (size_t)(blk * 96 + rb) * 128;
            #pragma unroll
            for (int t = 0; t < 16; t++) {
                int c = t * 8 + ((lane & 3) << 1);
                float pc0 = pcs[c], pc1 = pcs[c + 1];
                float y0 = hLO(accOh[t][0]) + pc0 + zA * fesm[iiA * 133 + c];
                float y1 = hHI(accOh[t][0]) + pc1 + zA * fesm[iiA * 133 + c + 1];
                float y2 = hLO(accOh[t][1]) + pc0 + zB * fesm[iiB * 133 + c];
                float y3 = hHI(accOh[t][1]) + pc1 + zB * fesm[iiB * 133 + c + 1];
                float g0 = c1g[c], g1 = c1g[c + 1], b0 = c1b[c], b1 = c1b[c + 1];
                float tA0 = (y0 - mA) * rA * g0 + b0;
                float tA1 = (y1 - mA) * rA * g1 + b1;
                float tB0 = (y2 - mB) * rB * g0 + b0;
                float tB1 = (y3 - mB) * rB * g1 + b1;
                __half hA0 = __float2half_rn(tA0), hA1 = __float2half_rn(tA1);
                __half hB0 = __float2half_rn(tB0), hB1 = __float2half_rn(tB1);
                *(uint32_t*)&g_th[br][0][rowA + c] = pk2h(hA0, hA1);
                *(uint32_t*)&g_th[br][1][rowA + c] =
                    pk2h(__float2half_rn(tA0 - __half2float(hA0)),
                         __float2half_rn(tA1 - __half2float(hA1)));
                *(uint32_t*)&g_th[br][0][rowB + c] = pk2h(hB0, hB1);
                *(uint32_t*)&g_th[br][1][rowB + c] =
                    pk2h(__float2half_rn(tB0 - __half2float(hB0)),
                         __float2half_rn(tB1 - __half2float(hB1)));
            }
        }
        __syncthreads();
    }
}

// ------------------------- K3: FFN per-branch CTA (2 CTAs/SM) -------------------
#define TAH_OFF 0        /* 128 x 272 = 34816 */
#define W1B_OFF 34816    /* 2 x 17408 */
#define W2B_OFF 69632    /* 2 x 18432 */
#define B1H_OFF 106496   /* 512 half = 1024 */
#define GWS_OFF 107520   /* 128 float */
#define B2S_OFF 108032   /* 128 float */
#define SM3 108544

__global__ __launch_bounds__(256, 2)
void ffn_mma(const float* __restrict__ b1g, const float* __restrict__ b2g,
             float* __restrict__ out) {
    extern __shared__ char smc[];
    uint32_t sb = cvta_s(smc);
    int tid = threadIdx.x, wid = tid >> 5, lane = tid & 31;
    int tile = blockIdx.x;
    int br = blockIdx.y;
    int g = lane >> 3;
    int m0 = wid * 16;

    __half* b1h = (__half*)(smc + B1H_OFF);
    float* gws = (float*)(smc + GWS_OFF);
    float* b2s = (float*)(smc + B2S_OFF);
    for (int idx = tid; idx < 512; idx += 256) b1h[idx] = __float2half_rn(b1g[idx]);
    if (tid < 128) { gws[tid] = g_gw[br][tid]; }
    else { b2s[tid - 128] = b2g[tid - 128]; }

    // stage t tile (hi plane) + chunk-0 weights, all via cp.async (one group)
    {
        const char* tsrc = (const char*)&g_th[br][0][(size_t)tile * 16384];
        for (int i = tid; i < 2048; i += 256) {
            int row = i >> 4, col = i & 15;
            CPA16(sb + TAH_OFF + row * 272 + col * 16, tsrc + row * 256 + col * 16);
        }
        uint32_t w1d = sb + W1B_OFF;
        for (int i = tid; i < 1024; i += 256) {
            int row = i >> 4, col = i & 15;
            CPA16(w1d + row * 272 + col * 16, (const char*)&g_w1h[0][0] + row * 256 + col * 16);
        }
        uint32_t w2d = sb + W2B_OFF;
        for (int i = tid; i < 1024; i += 256) {
            int row = i >> 3, col = i & 7;
            CPA16(w2d + row * 144 + col * 16, (const char*)&g_w2h[0][0] + row * 1024 + col * 16);
        }
        CPA_COMMIT();
    }

    uint32_t aRowOff = (uint32_t)((lane & 7) + ((g & 1) << 3));
    uint32_t aKOff   = (uint32_t)((g >> 1) << 4);
    uint32_t bPart272 = (uint32_t)(((lane & 7) + ((g >> 1) << 3)) * 272 + ((g & 1) << 4));
    uint32_t bPart144 = (uint32_t)(((lane & 7) + ((g >> 1) << 3)) * 144 + ((g & 1) << 4));
    uint32_t aBaseRow = (uint32_t)m0 + aRowOff;

    float accF[16][4];
    #pragma unroll
    for (int q = 0; q < 16; q++)
        #pragma unroll
        for (int v = 0; v < 4; v++) accF[q][v] = 0.f;

    for (int ch = 0; ch < 8; ch++) {
        if (ch < 7) {
            int nc = ch + 1, nb = nc & 1;
            uint32_t w1d = sb + W1B_OFF + nb * 17408;
            const char* w1src = (const char*)&g_w1h[nc * 64][0];
            for (int i = tid; i < 1024; i += 256) {
                int row = i >> 4, col = i & 15;
                CPA16(w1d + row * 272 + col * 16, w1src + row * 256 + col * 16);
            }
            uint32_t w2d = sb + W2B_OFF + nb * 18432;
            const char* w2src = (const char*)&g_w2h[0][0] + nc * 128;
            for (int i = tid; i < 1024; i += 256) {
                int row = i >> 3, col = i & 7;
                CPA16(w2d + row * 144 + col * 16, w2src + row * 1024 + col * 16);
            }
            CPA_COMMIT();
            asm volatile("cp.async.wait_group 1;" ::: "memory");
        } else {
            asm volatile("cp.async.wait_group 0;" ::: "memory");
        }
        __syncthreads();

        int cb = ch & 1;
        uint32_t acc1h[8][2];
        #pragma unroll
        for (int q = 0; q < 8; q++) { acc1h[q][0] = 0u; acc1h[q][1] = 0u; }
        uint32_t aHi = sb + TAH_OFF + aBaseRow * 272u + aKOff;
        uint32_t w1b = sb + W1B_OFF + cb * 17408 + bPart272;
        #pragma unroll
        for (int k = 0; k < 8; k++) {
            uint32_t h0, h1, h2, h3;
            ldsm4(aHi + (uint32_t)k * 32u, h0, h1, h2, h3);
            #pragma unroll
            for (int q = 0; q < 4; q++) {
                uint32_t r0, r1, r2, r3;
                ldsm4(w1b + (uint32_t)(q * 16 * 272) + (uint32_t)k * 32u, r0, r1, r2, r3);
                mma_f16h(acc1h[2 * q],     h0, h1, h2, h3, r0, r1);
                mma_f16h(acc1h[2 * q + 1], h0, h1, h2, h3, r2, r3);
            }
        }
        uint32_t w2b = sb + W2B_OFF + cb * 18432 + bPart144;
        #pragma unroll
        for (int ks = 0; ks < 4; ks++) {
            int cc0 = ch * 64 + (2 * ks) * 8 + ((lane & 3) << 1);
            uint32_t bw0 = *(uint32_t*)(smc + B1H_OFF + cc0 * 2);
            uint32_t bw1 = *(uint32_t*)(smc + B1H_OFF + (cc0 + 8) * 2);
            uint32_t ah0 = relu_add_h2(acc1h[2 * ks][0],     bw0);
            uint32_t ah1 = relu_add_h2(acc1h[2 * ks][1],     bw0);
            uint32_t ah2 = relu_add_h2(acc1h[2 * ks + 1][0], bw1);
            uint32_t ah3 = relu_add_h2(acc1h[2 * ks + 1][1], bw1);
            #pragma unroll
            for (int q = 0; q < 8; q++) {
                uint32_t r0, r1, r2, r3;
                ldsm4(w2b + (uint32_t)(q * 16 * 144) + (uint32_t)ks * 32u, r0, r1, r2, r3);
                mma_f16(accF[2 * q],     ah0, ah1, ah2, ah3, r0, r1);
                mma_f16(accF[2 * q + 1], ah0, ah1, ah2, ah3, r2, r3);
            }
        }
        __syncthreads();
    }

    // ---- epilogue: residual (hi from smem, lo from global) + fused LN2 + head ----
    int mrow = m0 + (lane >> 2);
    const __half* glo = &g_th[br][1][((size_t)tile * 128 + mrow) * 128];
    float sA0 = 0.f, sA1 = 0.f, sA2 = 0.f, sB0 = 0.f, sB1 = 0.f, sB2 = 0.f;
    #pragma unroll
    for (int t = 0; t < 16; t++) {
        int c = t * 8 + ((lane & 3) << 1);
        uint32_t hiA = *(uint32_t*)(smc + TAH_OFF + mrow * 272 + c * 2);
        uint32_t hiB = *(uint32_t*)(smc + TAH_OFF + (mrow + 8) * 272 + c * 2);
        uint32_t loA = *(const uint32_t*)&glo[c];
        uint32_t loB = *(const uint32_t*)&glo[8 * 128 + c];
        float t0a = hLO(hiA) + hLO(loA), t1a = hHI(hiA) + hHI(loA);
        float t0b = hLO(hiB) + hLO(loB), t1b = hHI(hiB) + hHI(loB);
        float bz0 = b2s[c], bz1 = b2s[c + 1];
        float g0 = gws[c], g1 = gws[c + 1];
        float y0 = accF[t][0] + t0a + bz0;
        float y1 = accF[t][1] + t1a + bz1;
        float y2 = accF[t][2] + t0b + bz0;
        float y3 = accF[t][3] + t1b + bz1;
        sA0 += y0 + y1; sA1 += y0 * y0 + y1 * y1; sA2 += y0 * g0 + y1 * g1;
        sB0 += y2 + y3; sB1 += y2 * y2 + y3 * y3; sB2 += y2 * g0 + y3 * g1;
    }
    #pragma unroll
    for (int m = 1; m < 4; m <<= 1) {
        sA0 += __shfl_xor_sync(0xffffffffu, sA0, m);
        sA1 += __shfl_xor_sync(0xffffffffu, sA1, m);
        sA2 += __shfl_xor_sync(0xffffffffu, sA2, m);
        sB0 += __shfl_xor_sync(0xffffffffu, sB0, m);
        sB1 += __shfl_xor_sync(0xffffffffu, sB1, m);
        sB2 += __shfl_xor_sync(0xffffffffu, sB2, m);
    }
    float sgw = g_sc[br][0], cst = g_sc[br][1];
    float mean = sA0 * (1.f / 128.f);
    float var = sA1 * (1.f / 128.f) - mean * mean;
    float resA = (sA2 - mean * sgw) * rsqrtf(var + 1e-5f) + cst;
    float meanb = sB0 * (1.f / 128.f);
    float varb = sB1 * (1.f / 128.f) - meanb * meanb;
    float resB = (sB2 - meanb * sgw) * rsqrtf(varb + 1e-5f) + cst;

    if ((lane & 3) == 0) {
        atomicAdd(&out[(size_t)tile * 128 + mrow], resA);
        atomicAdd(&out[(size_t)tile * 128 + mrow + 8], resB);
    }
}

// ------------------------- launch -------------------------
extern "C" void kernel_launch(void* const* d_in, const int* in_sizes, int n_in,
                              void* d_out, int out_size) {
    const float* z    = (const float*)d_in[0];
    const float* fe   = (const float*)d_in[1];
    const float* inwp = (const float*)d_in[2];
    const float* inbp = (const float*)d_in[3];
    const float* outwp= (const float*)d_in[4];
    const float* outbp= (const float*)d_in[5];
    const float* inwf = (const float*)d_in[6];
    const float* inbf = (const float*)d_in[7];
    const float* outwf= (const float*)d_in[8];
    const float* outbf= (const float*)d_in[9];
    const float* ln1g = (const float*)d_in[10];
    const float* ln1b = (const float*)d_in[11];
    const float* w1   = (const float*)d_in[12];
    const float* b1   = (const float*)d_in[13];
    const float* w2   = (const float*)d_in[14];
    const float* b2   = (const float*)d_in[15];
    const float* ln2g = (const float*)d_in[16];
    const float* ln2b = (const float*)d_in[17];
    const float* oppw = (const float*)d_in[18];
    const float* oppb = (const float*)d_in[19];
    const float* opfw = (const float*)d_in[20];
    const float* opfb = (const float*)d_in[21];
    const float* alog = (const float*)d_in[22];
    const float* bp   = (const float*)d_in[23];
    const float* bf   = (const float*)d_in[24];

    int B = in_sizes[0] / Hx;
    int tiles = (B * Hx) / 128;
    cudaFuncSetAttribute(attn_k, cudaFuncAttributeMaxDynamicSharedMemorySize, K2BYTES);
    cudaFuncSetAttribute(ffn_mma, cudaFuncAttributeMaxDynamicSharedMemorySize, SM3);

    pre_qkv<<<dim3(6, 8), 256>>>(fe, inwp, inwf);
    pre_misc<<<dim3(2, 8), 256>>>(inbp, inbf, outwp, outbp, outwf, outbf,
                                  ln2g, ln2b, oppw, oppb, opfw, opfb, alog, bp, bf);
    pre_wimg<<<256, 256>>>(w1, w2);
    attn_k<<<B / 4, 256, K2BYTES>>>(z, fe, ln1g, ln1b, (float*)d_out);
    ffn_mma<<<dim3(tiles, 2), 256, SM3>>>(b1, b2, (float*)d_out);
}

// round 17
// speedup vs baseline: 1.0929x; 1.0929x over previous
#include <cuda_runtime.h>
#include <cuda_fp16.h>
#include <math.h>
#include <stdint.h>

#define Hx 24
#define Dx 128
#define NHx 4
#define DHx 32
#define RS32 0.17677669529663687f

// ------------------------- device globals -------------------------
__device__ float g_E[2][3][Hx][Dx];
__device__ float g_Gt[2][Hx][NHx*Hx];
__device__ float g_Mkt[2][Hx][NHx*Hx];
__device__ float g_gq[2][NHx][Hx];
__device__ float g_gk[2][NHx][Hx];
__device__ __align__(16) __half g_Ph[2][Dx][104];
__device__ float g_Pc[2][Dx];
__device__ float g_gw[2][Dx];
__device__ float g_sc[2][2];
__device__ __half g_th[2][25165824u];   // t in fp16 (hi only), [br][row*128+c]
__device__ __half g_w1h[512][128];
__device__ __half g_w2h[128][512];

// ------------------------- helpers -------------------------
__device__ __forceinline__ uint32_t cvta_s(const void* p) {
    uint32_t a;
    asm("{ .reg .u64 t; cvta.to.shared.u64 t, %1; cvt.u32.u64 %0, t; }" : "=r"(a) : "l"(p));
    return a;
}
__device__ __forceinline__ void ldsm4(uint32_t addr, uint32_t& r0, uint32_t& r1,
                                      uint32_t& r2, uint32_t& r3) {
    asm volatile("ldmatrix.sync.aligned.m8n8.x4.shared.b16 {%0,%1,%2,%3}, [%4];"
                 : "=r"(r0), "=r"(r1), "=r"(r2), "=r"(r3) : "r"(addr));
}
__device__ __forceinline__ void mma_f16(float d[4], uint32_t a0, uint32_t a1, uint32_t a2,
                                        uint32_t a3, uint32_t b0, uint32_t b1) {
    asm volatile("mma.sync.aligned.m16n8k16.row.col.f32.f16.f16.f32 "
                 "{%0,%1,%2,%3}, {%4,%5,%6,%7}, {%8,%9}, {%0,%1,%2,%3};"
                 : "+f"(d[0]), "+f"(d[1]), "+f"(d[2]), "+f"(d[3])
                 : "r"(a0), "r"(a1), "r"(a2), "r"(a3), "r"(b0), "r"(b1));
}
__device__ __forceinline__ void mma_f16h(uint32_t d[2], uint32_t a0, uint32_t a1, uint32_t a2,
                                         uint32_t a3, uint32_t b0, uint32_t b1) {
    asm volatile("mma.sync.aligned.m16n8k16.row.col.f16.f16.f16.f16 "
                 "{%0,%1}, {%2,%3,%4,%5}, {%6,%7}, {%0,%1};"
                 : "+r"(d[0]), "+r"(d[1])
                 : "r"(a0), "r"(a1), "r"(a2), "r"(a3), "r"(b0), "r"(b1));
}
__device__ __forceinline__ uint32_t pk2h(__half e0, __half e1) {
    return (uint32_t)__half_as_ushort(e0) | ((uint32_t)__half_as_ushort(e1) << 16);
}
__device__ __forceinline__ float hLO(uint32_t v) {
    return __half2float(__ushort_as_half((unsigned short)(v & 0xFFFFu)));
}
__device__ __forceinline__ float hHI(uint32_t v) {
    return __half2float(__ushort_as_half((unsigned short)(v >> 16)));
}
__device__ __forceinline__ uint32_t relu_add_h2(uint32_t a, uint32_t b) {
    __half2 r = __hmax2(__hadd2(*(__half2*)&a, *(__half2*)&b),
                        __floats2half2_rn(0.f, 0.f));
    return *(uint32_t*)&r;
}
#define CPA16(d, s) asm volatile("cp.async.cg.shared.global [%0], [%1], 16;" :: "r"(d), "l"(s))
#define CPA_COMMIT() asm volatile("cp.async.commit_group;" ::: "memory")

// ------------------------- precompute 1 -------------------------
__global__ void pre_qkv(const float* __restrict__ fe, const float* __restrict__ inwp,
                        const float* __restrict__ inwf) {
    int br = blockIdx.x / 3, which = blockIdx.x % 3;
    const float* W = (br ? inwf : inwp) + which * Dx * Dx;
    __shared__ float fes[Hx * Dx];
    for (int idx = threadIdx.x; idx < Hx * Dx; idx += 256) fes[idx] = fe[idx];
    __syncthreads();
    for (int idx = blockIdx.y * 256 + threadIdx.x; idx < Hx * Dx; idx += 2048) {
        int i = idx >> 7, c = idx & 127;
        float s = 0.f;
        #pragma unroll 8
        for (int d = 0; d < Dx; d++) s += fes[i * Dx + d] * W[c * Dx + d];
        g_E[br][which][i][c] = s;
    }
}

// ------------------------- precompute 2 -------------------------
__global__ void pre_misc(const float* __restrict__ inbp, const float* __restrict__ inbf,
                         const float* __restrict__ outwp, const float* __restrict__ outbp,
                         const float* __restrict__ outwf, const float* __restrict__ outbf,
                         const float* __restrict__ ln2g, const float* __restrict__ ln2b,
                         const float* __restrict__ oppw, const float* __restrict__ oppb,
                         const float* __restrict__ opfw, const float* __restrict__ opfb,
                         const float* __restrict__ alog,
                         const float* __restrict__ biasp, const float* __restrict__ biasf) {
    int br = blockIdx.x, gy = blockIdx.y;
    const float* inb  = br ? inbf  : inbp;
    const float* outw = br ? outwf : outwp;
    const float* outb = br ? outbf : outbp;
    const float* opw  = br ? opfw  : oppw;
    const float* opb  = br ? opfb  : oppb;
    const float* bias = br ? biasf : biasp;
    const float* qb = inb, *kb = inb + Dx, *vb = inb + 2 * Dx;
    __shared__ float g0s[NHx];
    int tid = threadIdx.x;
    if (tid < NHx) {
        float s = 0.f;
        for (int d = 0; d < DHx; d++) s += qb[tid * DHx + d] * kb[tid * DHx + d];
        g0s[tid] = s * RS32;
    }
    __syncthreads();
    int base = gy * 256 + tid;
    for (int idx = base; idx < NHx * Hx; idx += 2048) {
        int n = idx / Hx, i = idx % Hx;
        float s1 = 0.f, s2 = 0.f;
        for (int d = 0; d < DHx; d++) {
            s1 += g_E[br][0][i][n * DHx + d] * kb[n * DHx + d];
            s2 += g_E[br][1][i][n * DHx + d] * qb[n * DHx + d];
        }
        g_gq[br][n][i] = s1 * RS32;
        g_gk[br][n][i] = s2 * RS32;
    }
    for (int idx = base; idx < NHx * Hx * Hx; idx += 2048) {
        int n = idx / (Hx * Hx), i = (idx / Hx) % Hx, j = idx % Hx;
        float s = 0.f;
        for (int d = 0; d < DHx; d++)
            s += g_E[br][0][i][n * DHx + d] * g_E[br][1][j][n * DHx + d];
        g_Gt[br][j][n * Hx + i] = s * RS32;
        bool valid = (br == 0) ? (j <= i) : (j >= i);
        g_Mkt[br][j][n * Hx + i] = valid ? bias[j - i + Hx - 1] + g0s[n] : -1e30f;
    }
    for (int idx = base; idx < NHx * Hx * Dx; idx += 2048) {
        int k = idx >> 7, c = idx & 127;
        int n = k / Hx, j = k % Hx;
        float s = 0.f;
        for (int d = 0; d < DHx; d++)
            s += outw[c * Dx + n * DHx + d] * g_E[br][2][j][n * DHx + d];
        g_Ph[br][c][k] = __float2half_rn(s);
    }
    if (gy == 0) {
        float e0 = expf(alog[0]), e1 = expf(alog[1]);
        float alpha = (br == 0 ? e0 : e1) / (e0 + e1);
        for (int idx = tid; idx < Dx; idx += 256) {
            float s = outb[idx];
            for (int m = 0; m < Dx; m++) s += outw[idx * Dx + m] * vb[m];
            g_Pc[br][idx] = s;
            g_gw[br][idx] = ln2g[idx] * opw[idx] * alpha;
        }
        __syncthreads();
        __threadfence();
        if (tid == 0) {
            float sgw = 0.f, cst = 0.f;
            for (int c = 0; c < Dx; c++) { sgw += g_gw[br][c]; cst += ln2b[c] * opw[c]; }
            g_sc[br][0] = sgw;
            g_sc[br][1] = alpha * (cst + opb[0]);
        }
    }
}

// ------------------------- precompute 3: fp16 weight images -------------------------
__global__ void pre_wimg(const float* __restrict__ w1, const float* __restrict__ w2) {
    int idx = blockIdx.x * 256 + threadIdx.x;
    if (idx >= 65536) return;
    {
        int f = idx >> 7, c = idx & 127;
        g_w1h[f][c] = __float2half_rn(w1[idx]);
    }
    {
        int n = idx >> 9, ff = idx & 511;
        g_w2h[n][ff] = __float2half_rn(w2[idx]);
    }
}

// ------------------------- K2: attention (mma.sync) + LN1 -> fp16 t ----------
#define FE0 480
#define WH0 3672
#define PH0 8664
#define K2BYTES 61280

__global__ __launch_bounds__(256)
void attn_k(const float* __restrict__ z, const float* __restrict__ fe,
            const float* __restrict__ ln1g, const float* __restrict__ ln1b,
            float* __restrict__ out) {
    extern __shared__ float sm[];
    float* zsm  = sm;
    float* c1g  = sm + 96;
    float* c1b  = sm + 224;
    float* pcs  = sm + 352;
    float* fesm = sm + FE0;
    __half* Wh  = (__half*)(sm + WH0);
    uint32_t sb = cvta_s(sm);
    uint32_t WhB = sb + WH0 * 4;
    uint32_t PhB = sb + PH0 * 4;
    int tid = threadIdx.x, wid = tid >> 5, lane = tid & 31;
    int g = lane >> 3;
    int blk = blockIdx.x;

    if (tid < 96) { zsm[tid] = z[blk * 96 + tid]; out[blk * 96 + tid] = 0.f; }
    if (tid >= 128) { c1g[tid - 128] = ln1g[tid - 128]; c1b[tid - 128] = ln1b[tid - 128]; }
    for (int idx = tid; idx < Hx * Dx; idx += 256)
        fesm[(idx >> 7) * 133 + (idx & 127)] = fe[idx];
    __syncthreads();

    for (int br = 0; br < 2; br++) {
        {
            const uint4* ps = (const uint4*)&g_Ph[br][0][0];
            uint4* pd = (uint4*)(sm + PH0);
            for (int i = tid; i < 1664; i += 256) pd[i] = ps[i];
            if (tid < 128) pcs[tid] = g_Pc[br][tid];
        }
        for (int rs = tid; rs < 384; rs += 256) {
            int bb = rs / 96, rem = rs % 96, n = rem / 24, i = rem % 24;
            int x = n * Hx + i;
            float zi = zsm[bb * 24 + i];
            const float* Gt = &g_Gt[br][0][x];
            const float* Mt = &g_Mkt[br][0][x];
            const float* gkp = &g_gk[br][n][0];
            float gq = g_gq[br][n][i];
            float s[24]; float mx = -1e30f;
            #pragma unroll
            for (int j = 0; j < 24; j++) {
                float zj = zsm[bb * 24 + j];
                float v = zi * zj * Gt[j * 96] + zi * gq + zj * gkp[j] + Mt[j * 96];
                s[j] = v; mx = fmaxf(mx, v);
            }
            float sum = 0.f;
            #pragma unroll
            for (int j = 0; j < 24; j++) { s[j] = __expf(fmaxf(s[j] - mx, -80.f)); sum += s[j]; }
            float inv = 1.f / sum;
            __half* wrow = &Wh[(bb * 24 + i) * 104 + n * 24];
            #pragma unroll
            for (int j = 0; j < 24; j += 2) {
                *(uint32_t*)&wrow[j] = pk2h(__float2half_rn(s[j] * inv * zsm[bb * 24 + j]),
                                            __float2half_rn(s[j + 1] * inv * zsm[bb * 24 + j + 1]));
            }
        }
        __syncthreads();

        if (wid < 6) {
            float accO[16][4];
            #pragma unroll
            for (int q = 0; q < 16; q++)
                #pragma unroll
                for (int v = 0; v < 4; v++) accO[q][v] = 0.f;
            uint32_t aAddr = WhB + (uint32_t)(wid * 16 + (lane & 7) + ((g & 1) << 3)) * 208u
                                 + (uint32_t)((g >> 1) << 4);
            uint32_t bAddr = PhB + (uint32_t)((lane & 7) + ((g >> 1) << 3)) * 208u
                                 + (uint32_t)((g & 1) << 4);
            #pragma unroll
            for (int k = 0; k < 6; k++) {
                uint32_t a0, a1, a2, a3;
                ldsm4(aAddr + (uint32_t)k * 32u, a0, a1, a2, a3);
                #pragma unroll
                for (int q = 0; q < 8; q++) {
                    uint32_t r0, r1, r2, r3;
                    ldsm4(bAddr + (uint32_t)(q * 16 * 208) + (uint32_t)k * 32u, r0, r1, r2, r3);
                    mma_f16(accO[2 * q],     a0, a1, a2, a3, r0, r1);
                    mma_f16(accO[2 * q + 1], a0, a1, a2, a3, r2, r3);
                }
            }
            int ra = wid * 16 + (lane >> 2);
            int rb = ra + 8;
            int iiA = ra % 24, iiB = rb % 24;
            float zA = zsm[ra], zB = zsm[rb];
            float sA0 = 0.f, sA1 = 0.f, sB0 = 0.f, sB1 = 0.f;
            #pragma unroll
            for (int t = 0; t < 16; t++) {
                int c = t * 8 + ((lane & 3) << 1);
                float pc0 = pcs[c], pc1 = pcs[c + 1];
                float y0 = accO[t][0] + pc0 + zA * fesm[iiA * 133 + c];
                float y1 = accO[t][1] + pc1 + zA * fesm[iiA * 133 + c + 1];
                float y2 = accO[t][2] + pc0 + zB * fesm[iiB * 133 + c];
                float y3 = accO[t][3] + pc1 + zB * fesm[iiB * 133 + c + 1];
                accO[t][0] = y0; accO[t][1] = y1; accO[t][2] = y2; accO[t][3] = y3;
                sA0 += y0 + y1; sA1 += y0 * y0 + y1 * y1;
                sB0 += y2 + y3; sB1 += y2 * y2 + y3 * y3;
            }
            #pragma unroll
            for (int m = 1; m < 4; m <<= 1) {
                sA0 += __shfl_xor_sync(0xffffffffu, sA0, m);
                sA1 += __shfl_xor_sync(0xffffffffu, sA1, m);
                sB0 += __shfl_xor_sync(0xffffffffu, sB0, m);
                sB1 += __shfl_xor_sync(0xffffffffu, sB1, m);
            }
            float mA = sA0 * (1.f / 128.f);
            float rA = rsqrtf(sA1 * (1.f / 128.f) - mA * mA + 1e-5f);
            float mB = sB0 * (1.f / 128.f);
            float rB = rsqrtf(sB1 * (1.f / 128.f) - mB * mB + 1e-5f);
            __half* dstA = &g_th[br][(size_t)(blk * 96 + ra) * 128];
            __half* dstB = &g_th[br][(size_t)(blk * 96 + rb) * 128];
            #pragma unroll
            for (int t = 0; t < 16; t++) {
                int c = t * 8 + ((lane & 3) << 1);
                float g0 = c1g[c], g1 = c1g[c + 1], b0 = c1b[c], b1 = c1b[c + 1];
                float tA0 = (accO[t][0] - mA) * rA * g0 + b0;
                float tA1 = (accO[t][1] - mA) * rA * g1 + b1;
                float tB0 = (accO[t][2] - mB) * rB * g0 + b0;
                float tB1 = (accO[t][3] - mB) * rB * g1 + b1;
                *(uint32_t*)&dstA[c] = pk2h(__float2half_rn(tA0), __float2half_rn(tA1));
                *(uint32_t*)&dstB[c] = pk2h(__float2half_rn(tB0), __float2half_rn(tB1));
            }
        }
        __syncthreads();
    }
}

// ------------------------- K3: FFN per-branch CTA (2 CTAs/SM) -------------------
#define TAH_OFF 0        /* 128 x 272 = 34816 */
#define W1B_OFF 34816    /* 2 x 17408 */
#define W2B_OFF 69632    /* 2 x 18432 */
#define B1H_OFF 106496   /* 512 half = 1024 */
#define GWS_OFF 107520   /* 128 float */
#define B2S_OFF 108032   /* 128 float */
#define SM3 108544

__global__ __launch_bounds__(256, 2)
void ffn_mma(const float* __restrict__ b1g, const float* __restrict__ b2g,
             float* __restrict__ out) {
    extern __shared__ char smc[];
    uint32_t sb = cvta_s(smc);
    int tid = threadIdx.x, wid = tid >> 5, lane = tid & 31;
    int tile = blockIdx.x;
    int br = blockIdx.y;
    int g = lane >> 3;
    int m0 = wid * 16;

    __half* b1h = (__half*)(smc + B1H_OFF);
    float* gws = (float*)(smc + GWS_OFF);
    float* b2s = (float*)(smc + B2S_OFF);
    for (int idx = tid; idx < 512; idx += 256) b1h[idx] = __float2half_rn(b1g[idx]);
    if (tid < 128) { gws[tid] = g_gw[br][tid]; }
    else { b2s[tid - 128] = b2g[tid - 128]; }

    // stage t tile (fp16) + chunk-0 weights, all via cp.async (one group)
    {
        const char* tsrc = (const char*)&g_th[br][(size_t)tile * 16384];
        for (int i = tid; i < 2048; i += 256) {
            int row = i >> 4, col = i & 15;
            CPA16(sb + TAH_OFF + row * 272 + col * 16, tsrc + row * 256 + col * 16);
        }
        uint32_t w1d = sb + W1B_OFF;
        for (int i = tid; i < 1024; i += 256) {
            int row = i >> 4, col = i & 15;
            CPA16(w1d + row * 272 + col * 16, (const char*)&g_w1h[0][0] + row * 256 + col * 16);
        }
        uint32_t w2d = sb + W2B_OFF;
        for (int i = tid; i < 1024; i += 256) {
            int row = i >> 3, col = i & 7;
            CPA16(w2d + row * 144 + col * 16, (const char*)&g_w2h[0][0] + row * 1024 + col * 16);
        }
        CPA_COMMIT();
    }

    uint32_t aRowOff = (uint32_t)((lane & 7) + ((g & 1) << 3));
    uint32_t aKOff   = (uint32_t)((g >> 1) << 4);
    uint32_t bPart272 = (uint32_t)(((lane & 7) + ((g >> 1) << 3)) * 272 + ((g & 1) << 4));
    uint32_t bPart144 = (uint32_t)(((lane & 7) + ((g >> 1) << 3)) * 144 + ((g & 1) << 4));
    uint32_t aBaseRow = (uint32_t)m0 + aRowOff;

    float accF[16][4];
    #pragma unroll
    for (int q = 0; q < 16; q++)
        #pragma unroll
        for (int v = 0; v < 4; v++) accF[q][v] = 0.f;

    for (int ch = 0; ch < 8; ch++) {
        if (ch < 7) {
            int nc = ch + 1, nb = nc & 1;
            uint32_t w1d = sb + W1B_OFF + nb * 17408;
            const char* w1src = (const char*)&g_w1h[nc * 64][0];
            for (int i = tid; i < 1024; i += 256) {
                int row = i >> 4, col = i & 15;
                CPA16(w1d + row * 272 + col * 16, w1src + row * 256 + col * 16);
            }
            uint32_t w2d = sb + W2B_OFF + nb * 18432;
            const char* w2src = (const char*)&g_w2h[0][0] + nc * 128;
            for (int i = tid; i < 1024; i += 256) {
                int row = i >> 3, col = i & 7;
                CPA16(w2d + row * 144 + col * 16, w2src + row * 1024 + col * 16);
            }
            CPA_COMMIT();
            asm volatile("cp.async.wait_group 1;" ::: "memory");
        } else {
            asm volatile("cp.async.wait_group 0;" ::: "memory");
        }
        __syncthreads();

        int cb = ch & 1;
        uint32_t acc1h[8][2];
        #pragma unroll
        for (int q = 0; q < 8; q++) { acc1h[q][0] = 0u; acc1h[q][1] = 0u; }
        uint32_t aHi = sb + TAH_OFF + aBaseRow * 272u + aKOff;
        uint32_t w1b = sb + W1B_OFF + cb * 17408 + bPart272;
        #pragma unroll
        for (int k = 0; k < 8; k++) {
            uint32_t h0, h1, h2, h3;
            ldsm4(aHi + (uint32_t)k * 32u, h0, h1, h2, h3);
            #pragma unroll
            for (int q = 0; q < 4; q++) {
                uint32_t r0, r1, r2, r3;
                ldsm4(w1b + (uint32_t)(q * 16 * 272) + (uint32_t)k * 32u, r0, r1, r2, r3);
                mma_f16h(acc1h[2 * q],     h0, h1, h2, h3, r0, r1);
                mma_f16h(acc1h[2 * q + 1], h0, h1, h2, h3, r2, r3);
            }
        }
        uint32_t w2b = sb + W2B_OFF + cb * 18432 + bPart144;
        #pragma unroll
        for (int ks = 0; ks < 4; ks++) {
            int cc0 = ch * 64 + (2 * ks) * 8 + ((lane & 3) << 1);
            uint32_t bw0 = *(uint32_t*)(smc + B1H_OFF + cc0 * 2);
            uint32_t bw1 = *(uint32_t*)(smc + B1H_OFF + (cc0 + 8) * 2);
            uint32_t ah0 = relu_add_h2(acc1h[2 * ks][0],     bw0);
            uint32_t ah1 = relu_add_h2(acc1h[2 * ks][1],     bw0);
            uint32_t ah2 = relu_add_h2(acc1h[2 * ks + 1][0], bw1);
            uint32_t ah3 = relu_add_h2(acc1h[2 * ks + 1][1], bw1);
            #pragma unroll
            for (int q = 0; q < 8; q++) {
                uint32_t r0, r1, r2, r3;
                ldsm4(w2b + (uint32_t)(q * 16 * 144) + (uint32_t)ks * 32u, r0, r1, r2, r3);
                mma_f16(accF[2 * q],     ah0, ah1, ah2, ah3, r0, r1);
                mma_f16(accF[2 * q + 1], ah0, ah1, ah2, ah3, r2, r3);
            }
        }
        __syncthreads();
    }

    // ---- epilogue: residual (hi from smem) + fused LN2 + head ----
    int mrow = m0 + (lane >> 2);
    float sA0 = 0.f, sA1 = 0.f, sA2 = 0.f, sB0 = 0.f, sB1 = 0.f, sB2 = 0.f;
    #pragma unroll
    for (int t = 0; t < 16; t++) {
        int c = t * 8 + ((lane & 3) << 1);
        uint32_t hiA = *(uint32_t*)(smc + TAH_OFF + mrow * 272 + c * 2);
        uint32_t hiB = *(uint32_t*)(smc + TAH_OFF + (mrow + 8) * 272 + c * 2);
        float t0a = hLO(hiA), t1a = hHI(hiA);
        float t0b = hLO(hiB), t1b = hHI(hiB);
        float bz0 = b2s[c], bz1 = b2s[c + 1];
        float g0 = gws[c], g1 = gws[c + 1];
        float y0 = accF[t][0] + t0a + bz0;
        float y1 = accF[t][1] + t1a + bz1;
        float y2 = accF[t][2] + t0b + bz0;
        float y3 = accF[t][3] + t1b + bz1;
        sA0 += y0 + y1; sA1 += y0 * y0 + y1 * y1; sA2 += y0 * g0 + y1 * g1;
        sB0 += y2 + y3; sB1 += y2 * y2 + y3 * y3; sB2 += y2 * g0 + y3 * g1;
    }
    #pragma unroll
    for (int m = 1; m < 4; m <<= 1) {
        sA0 += __shfl_xor_sync(0xffffffffu, sA0, m);
        sA1 += __shfl_xor_sync(0xffffffffu, sA1, m);
        sA2 += __shfl_xor_sync(0xffffffffu, sA2, m);
        sB0 += __shfl_xor_sync(0xffffffffu, sB0, m);
        sB1 += __shfl_xor_sync(0xffffffffu, sB1, m);
        sB2 += __shfl_xor_sync(0xffffffffu, sB2, m);
    }
    float sgw = g_sc[br][0], cst = g_sc[br][1];
    float mean = sA0 * (1.f / 128.f);
    float var = sA1 * (1.f / 128.f) - mean * mean;
    float resA = (sA2 - mean * sgw) * rsqrtf(var + 1e-5f) + cst;
    float meanb = sB0 * (1.f / 128.f);
    float varb = sB1 * (1.f / 128.f) - meanb * meanb;
    float resB = (sB2 - meanb * sgw) * rsqrtf(varb + 1e-5f) + cst;

    if ((lane & 3) == 0) {
        atomicAdd(&out[(size_t)tile * 128 + mrow], resA);
        atomicAdd(&out[(size_t)tile * 128 + mrow + 8], resB);
    }
}

// ------------------------- launch -------------------------
extern "C" void kernel_launch(void* const* d_in, const int* in_sizes, int n_in,
                              void* d_out, int out_size) {
    const float* z    = (const float*)d_in[0];
    const float* fe   = (const float*)d_in[1];
    const float* inwp = (const float*)d_in[2];
    const float* inbp = (const float*)d_in[3];
    const float* outwp= (const float*)d_in[4];
    const float* outbp= (const float*)d_in[5];
    const float* inwf = (const float*)d_in[6];
    const float* inbf = (const float*)d_in[7];
    const float* outwf= (const float*)d_in[8];
    const float* outbf= (const float*)d_in[9];
    const float* ln1g = (const float*)d_in[10];
    const float* ln1b = (const float*)d_in[11];
    const float* w1   = (const float*)d_in[12];
    const float* b1   = (const float*)d_in[13];
    const float* w2   = (const float*)d_in[14];
    const float* b2   = (const float*)d_in[15];
    const float* ln2g = (const float*)d_in[16];
    const float* ln2b = (const float*)d_in[17];
    const float* oppw = (const float*)d_in[18];
    const float* oppb = (const float*)d_in[19];
    const float* opfw = (const float*)d_in[20];
    const float* opfb = (const float*)d_in[21];
    const float* alog = (const float*)d_in[22];
    const float* bp   = (const float*)d_in[23];
    const float* bf   = (const float*)d_in[24];

    int B = in_sizes[0] / Hx;
    int tiles = (B * Hx) / 128;
    cudaFuncSetAttribute(attn_k, cudaFuncAttributeMaxDynamicSharedMemorySize, K2BYTES);
    cudaFuncSetAttribute(ffn_mma, cudaFuncAttributeMaxDynamicSharedMemorySize, SM3);

    pre_qkv<<<dim3(6, 8), 256>>>(fe, inwp, inwf);
    pre_misc<<<dim3(2, 8), 256>>>(inbp, inbf, outwp, outbp, outwf, outbf,
                                  ln2g, ln2b, oppw, oppb, opfw, opfb, alog, bp, bf);
    pre_wimg<<<256, 256>>>(w1, w2);
    attn_k<<<B / 4, 256, K2BYTES>>>(z, fe, ln1g, ln1b, (float*)d_out);
    ffn_mma<<<dim3(tiles, 2), 256, SM3>>>(b1, b2, (float*)d_out);
}